// round 4
// baseline (speedup 1.0000x reference)
#include <cuda_runtime.h>
#include <cstdint>

#define IN  8192
#define OUT 8192
#define RW  1024               // packed word-rows (IN/8)
#define TPB 128                // 4 warps
#define OPB 32                 // outputs per CTA (one per lane)
#define KSPLIT 8               // K chunks across CTAs
#define ROWS_CTA (RW / KSPLIT) // 128 word-rows per CTA
#define NIT (ROWS_CTA / 4)     // 32 word-rows per warp

// Cross-CTA partials (no allocation allowed -> __device__ globals)
__device__ float g_part[KSPLIT][OUT];
__device__ float g_sx[KSPLIT];

// Build (1 + v_a/Sa, 1 + v_b/Sb) from two masked nibble windows and do one
// packed fma.rn.f32x2 with the raw x pair. Post-scale removes the bias later.
__device__ __forceinline__ void dq(unsigned long long& acc,
                                   unsigned a, unsigned ma,
                                   unsigned b, unsigned mb,
                                   unsigned long long xp) {
    asm("{\n\t"
        ".reg .b32 lo, hi;\n\t"
        ".reg .b64 v;\n\t"
        "lop3.b32 lo, %1, %2, 0x3F800000, 0xEA;\n\t"
        "lop3.b32 hi, %3, %4, 0x3F800000, 0xEA;\n\t"
        "mov.b64 v, {lo, hi};\n\t"
        "fma.rn.f32x2 %0, %5, v, %0;\n\t"
        "}"
        : "+l"(acc) : "r"(a), "r"(ma), "r"(b), "r"(mb), "l"(xp));
}

__device__ __forceinline__ float f32lo(unsigned long long a) {
    return __uint_as_float((unsigned)(a & 0xffffffffu));
}
__device__ __forceinline__ float f32hi(unsigned long long a) {
    return __uint_as_float((unsigned)(a >> 32));
}

// Slot -> (source, mask, scale):
//  s1 = w<<11 : n0 @[11:15) S=4096 | n1 @[15:19) S=256 | n2 @[19:23) S=16
//  w          : n3 @[12:16) S=2048 | n4 @[16:20) S=128
//  s2 = w>>9  : n5 @[11:15) S=4096 | n6 @[15:19) S=256 | n7 @[19:23) S=16
__global__ __launch_bounds__(TPB, 12)
void qmv1(const float* __restrict__ x, const int* __restrict__ qw) {
    __shared__ float red[4][OPB];
    __shared__ float sxw[4];

    const int lane = threadIdx.x & 31;
    const int wid  = threadIdx.x >> 5;
    const int obase = blockIdx.x * OPB;
    const int rbase = blockIdx.y * ROWS_CTA + wid * NIT;   // first word-row
    const int kbase = rbase * 8;

    // ---- per-slot x sums over this warp's 256 k values (warp-uniform) ----
    float S0, S1, S2, S3, S4, S5, S6, S7;
    {
        const float4* xg = reinterpret_cast<const float4*>(x + kbase);
        float4 xa = xg[lane * 2];
        float4 xb = xg[lane * 2 + 1];
        S0 = xa.x; S1 = xa.y; S2 = xa.z; S3 = xa.w;
        S4 = xb.x; S5 = xb.y; S6 = xb.z; S7 = xb.w;
        #pragma unroll
        for (int off = 16; off > 0; off >>= 1) {
            S0 += __shfl_xor_sync(0xffffffffu, S0, off);
            S1 += __shfl_xor_sync(0xffffffffu, S1, off);
            S2 += __shfl_xor_sync(0xffffffffu, S2, off);
            S3 += __shfl_xor_sync(0xffffffffu, S3, off);
            S4 += __shfl_xor_sync(0xffffffffu, S4, off);
            S5 += __shfl_xor_sync(0xffffffffu, S5, off);
            S6 += __shfl_xor_sync(0xffffffffu, S6, off);
            S7 += __shfl_xor_sync(0xffffffffu, S7, off);
        }
    }

    // ---- main loop: lane = output, warp shares row; x is broadcast L1 ----
    const unsigned* qp = reinterpret_cast<const unsigned*>(qw) +
                         (size_t)rbase * OUT + obase + lane;
    const ulonglong2* xr = reinterpret_cast<const ulonglong2*>(x) + 2 * rbase;

    unsigned long long a0 = 0, a1 = 0, a2 = 0, a3 = 0;

    #pragma unroll 4
    for (int i = 0; i < NIT; i++) {
        unsigned w = __ldcs(qp + (size_t)i * OUT);   // streaming: don't pollute L1
        ulonglong2 xA = xr[2 * i];                   // raw x pairs (k0,k1),(k2,k3)
        ulonglong2 xB = xr[2 * i + 1];               // (k4,k5),(k6,k7)
        unsigned sl = w * 2048u;                     // w<<11 on fma pipe (IMAD)
        unsigned sr = __umulhi(w, 1u << 23);         // w>>9  on fma pipe (IMAD.HI)
        dq(a0, sl, 0x00007800u, sl, 0x00078000u, xA.x);  // n0,n1
        dq(a1, sl, 0x00780000u, w,  0x0000F000u, xA.y);  // n2,n3
        dq(a2, w,  0x000F0000u, sr, 0x00007800u, xB.x);  // n4,n5
        dq(a3, sr, 0x00078000u, sr, 0x00780000u, xB.y);  // n6,n7
    }

    // ---- post-scale per class, remove Sx bias ----
    float d = (f32lo(a0) - S0) * 4096.f + (f32hi(a0) - S1) * 256.f
            + (f32lo(a1) - S2) * 16.f   + (f32hi(a1) - S3) * 2048.f
            + (f32lo(a2) - S4) * 128.f  + (f32hi(a2) - S5) * 4096.f
            + (f32lo(a3) - S6) * 256.f  + (f32hi(a3) - S7) * 16.f;

    red[wid][lane] = d;
    if (lane == 0)
        sxw[wid] = ((S0 + S1) + (S2 + S3)) + ((S4 + S5) + (S6 + S7));
    __syncthreads();

    if (wid == 0) {
        float t = (red[0][lane] + red[1][lane]) + (red[2][lane] + red[3][lane]);
        g_part[blockIdx.y][obase + lane] = t;
        if (lane == 0)   // identical value from every bx -> deterministic
            g_sx[blockIdx.y] = (sxw[0] + sxw[1]) + (sxw[2] + sxw[3]);
    }
}

__global__ void qmv2(const float* __restrict__ scales,
                     const float* __restrict__ zeros,
                     const float* __restrict__ bias,
                     float* __restrict__ out) {
    int o = blockIdx.x * blockDim.x + threadIdx.x;
    float p = 0.f, sx = 0.f;
    #pragma unroll
    for (int k = 0; k < KSPLIT; k++) p += g_part[k][o];
    #pragma unroll
    for (int k = 0; k < KSPLIT; k++) sx += g_sx[k];
    out[o] = bias[o] + scales[o] * p - zeros[o] * sx;
}

extern "C" void kernel_launch(void* const* d_in, const int* in_sizes, int n_in,
                              void* d_out, int out_size) {
    const float* x      = (const float*)d_in[0];
    const int*   qw     = (const int*)d_in[1];
    const float* scales = (const float*)d_in[2];
    const float* zeros  = (const float*)d_in[3];
    const float* bias   = (const float*)d_in[4];
    float* out = (float*)d_out;

    dim3 g1(OUT / OPB, KSPLIT);   // 256 x 8 = 2048 CTAs
    qmv1<<<g1, TPB>>>(x, qw);
    qmv2<<<OUT / 256, 256>>>(scales, zeros, bias, out);
}

// round 6
// speedup vs baseline: 1.4147x; 1.4147x over previous
#include <cuda_runtime.h>
#include <cstdint>

#define IN 8192
#define OUT 8192
#define RW 1024            // packed int32 rows (IN/8)
#define TPB 512            // 16 warps: 8 output-quads x 4 rowgroups per warp
#define OPB 32             // outputs per block
#define NRG 64             // concurrent row-groups
#define NIT (RW / NRG)     // 16 iterations per thread

// Exponent-OR dequant, 5 windows / 2 shifts per word (shifts are IMADs on fma pipe):
//  sl = w*2048 (w<<11): n0 @[11:15) S=4096 | n1 @[15:19) S=256 | n2 @[19:23) S=16
//  w  (unshifted)     : n3 @[12:16) S=2048 | n4 @[16:20) S=128
//  sr = w>>9 (umulhi) : n5 @[11:15) S=4096 | n6 @[15:19) S=256 | n7 @[19:23) S=16
// x' is prescaled by S per k%8; fma.rn.f32x2(x', 1+v/S) = x' + x*v.
// Sum(x') bias subtracted once at the end.
#define DQ(acc, ra, MA, rb, MB, xp)                              \
    asm("{\n\t"                                                  \
        ".reg .b32 lo, hi;\n\t"                                  \
        ".reg .b64 v;\n\t"                                       \
        "lop3.b32 lo, %1, " MA ", 0x3F800000, 0xEA;\n\t"         \
        "lop3.b32 hi, %2, " MB ", 0x3F800000, 0xEA;\n\t"         \
        "mov.b64 v, {lo, hi};\n\t"                               \
        "fma.rn.f32x2 %0, %3, v, %0;\n\t"                        \
        "}"                                                      \
        : "+l"(acc) : "r"(ra), "r"(rb), "l"(xp))

__device__ __forceinline__ float acc_sum(unsigned long long a, unsigned long long b) {
    return (__uint_as_float((unsigned)(a & 0xffffffffu)) +
            __uint_as_float((unsigned)(a >> 32))) +
           (__uint_as_float((unsigned)(b & 0xffffffffu)) +
            __uint_as_float((unsigned)(b >> 32)));
}

__global__ __launch_bounds__(TPB, 2)
void qmv_kernel(const float* __restrict__ x, const int* __restrict__ qw,
                const float* __restrict__ scales, const float* __restrict__ zeros,
                const float* __restrict__ bias, float* __restrict__ out) {
    __shared__ ulonglong2 xs2[IN / 4];   // prescaled x' pairs, 32 KB
    __shared__ float red[NRG][OPB];      // 8 KB
    __shared__ float r2[4][OPB];
    __shared__ float rs[16], rsp[16];

    const int tid  = threadIdx.x;
    const int lane = tid & 31;
    const int w    = tid >> 5;
    const int og   = lane & 7;                 // output quad 0..7
    const int rg   = (w << 2) | (lane >> 3);   // row-group 0..63

    // ---- stage x' pairs; scale pattern per k%8: 4096,256,16,2048,128,4096,256,16
    float sp = 0.f, spp = 0.f;
    const float4* xg = reinterpret_cast<const float4*>(x);
    #pragma unroll
    for (int i = tid; i < IN / 4; i += TPB) {
        float4 v = xg[i];
        sp += (v.x + v.y) + (v.z + v.w);
        float p0, p1, p2, p3;
        if (i & 1) {  // k%8 = 4..7
            p0 = v.x * 128.f;  p1 = v.y * 4096.f;
            p2 = v.z * 256.f;  p3 = v.w * 16.f;
        } else {      // k%8 = 0..3
            p0 = v.x * 4096.f; p1 = v.y * 256.f;
            p2 = v.z * 16.f;   p3 = v.w * 2048.f;
        }
        spp += (p0 + p1) + (p2 + p3);
        unsigned long long lo = ((unsigned long long)__float_as_uint(p1) << 32) |
                                __float_as_uint(p0);
        unsigned long long hi = ((unsigned long long)__float_as_uint(p3) << 32) |
                                __float_as_uint(p2);
        xs2[i] = make_ulonglong2(lo, hi);
    }
    #pragma unroll
    for (int o = 16; o > 0; o >>= 1) {
        sp  += __shfl_down_sync(0xffffffffu, sp, o);
        spp += __shfl_down_sync(0xffffffffu, spp, o);
    }
    if (lane == 0) { rs[w] = sp; rsp[w] = spp; }
    __syncthreads();

    // ---- main loop: 4 outputs (uint4), rows rg + 64*i, weight-only prefetch ----
    const uint4* qp = reinterpret_cast<const uint4*>(qw) +
                      (size_t)rg * (OUT / 4) + blockIdx.x * 8 + og;
    const size_t qstride = (size_t)NRG * (OUT / 4);

    unsigned long long a0A = 0, a0B = 0, a1A = 0, a1B = 0;
    unsigned long long a2A = 0, a2B = 0, a3A = 0, a3B = 0;

    uint4 wv = qp[0];

    #pragma unroll 4
    for (int i = 0; i < NIT; i++) {
        uint4 wn = make_uint4(0u, 0u, 0u, 0u);
        if (i + 1 < NIT) wn = qp[(size_t)(i + 1) * qstride];

        int r = rg + (i << 6);
        ulonglong2 xA = xs2[2 * r];       // pairs (k0,k1), (k2,k3)
        ulonglong2 xB = xs2[2 * r + 1];   // pairs (k4,k5), (k6,k7)

        unsigned sl, sr;
        // word 0 -> output o+0
        sl = wv.x * 2048u; sr = __umulhi(wv.x, 1u << 23);
        DQ(a0A, sl, "0x00007800", sl, "0x00078000", xA.x);   // n0,n1
        DQ(a0A, sl, "0x00780000", wv.x, "0x0000F000", xA.y); // n2,n3
        DQ(a0B, wv.x, "0x000F0000", sr, "0x00007800", xB.x); // n4,n5
        DQ(a0B, sr, "0x00078000", sr, "0x00780000", xB.y);   // n6,n7
        // word 1 -> output o+1
        sl = wv.y * 2048u; sr = __umulhi(wv.y, 1u << 23);
        DQ(a1A, sl, "0x00007800", sl, "0x00078000", xA.x);
        DQ(a1A, sl, "0x00780000", wv.y, "0x0000F000", xA.y);
        DQ(a1B, wv.y, "0x000F0000", sr, "0x00007800", xB.x);
        DQ(a1B, sr, "0x00078000", sr, "0x00780000", xB.y);
        // word 2 -> output o+2
        sl = wv.z * 2048u; sr = __umulhi(wv.z, 1u << 23);
        DQ(a2A, sl, "0x00007800", sl, "0x00078000", xA.x);
        DQ(a2A, sl, "0x00780000", wv.z, "0x0000F000", xA.y);
        DQ(a2B, wv.z, "0x000F0000", sr, "0x00007800", xB.x);
        DQ(a2B, sr, "0x00078000", sr, "0x00780000", xB.y);
        // word 3 -> output o+3
        sl = wv.w * 2048u; sr = __umulhi(wv.w, 1u << 23);
        DQ(a3A, sl, "0x00007800", sl, "0x00078000", xA.x);
        DQ(a3A, sl, "0x00780000", wv.w, "0x0000F000", xA.y);
        DQ(a3B, wv.w, "0x000F0000", sr, "0x00007800", xB.x);
        DQ(a3B, sr, "0x00078000", sr, "0x00780000", xB.y);

        wv = wn;
    }

    {
        float4 f = make_float4(acc_sum(a0A, a0B), acc_sum(a1A, a1B),
                               acc_sum(a2A, a2B), acc_sum(a3A, a3B));
        *reinterpret_cast<float4*>(&red[rg][og * 4]) = f;
    }
    __syncthreads();

    // ---- reduce 64 row-groups per output ----
    if (tid < 128) {
        int o = tid & 31, seg = tid >> 5;
        float s = 0.f;
        #pragma unroll
        for (int j = 0; j < 16; j++) s += red[seg * 16 + j][o];
        r2[seg][o] = s;
    }
    __syncthreads();

    if (tid < OPB) {
        float dot = (r2[0][tid] + r2[1][tid]) + (r2[2][tid] + r2[3][tid]);
        float sx = 0.f, sxp = 0.f;
        #pragma unroll
        for (int i = 0; i < 16; i++) { sx += rs[i]; sxp += rsp[i]; }
        dot -= sxp;   // remove implicit-1.0 bias
        int o = blockIdx.x * OPB + tid;
        out[o] = bias[o] + scales[o] * dot - zeros[o] * sx;
    }
}

extern "C" void kernel_launch(void* const* d_in, const int* in_sizes, int n_in,
                              void* d_out, int out_size) {
    const float* x      = (const float*)d_in[0];
    const int*   qw     = (const int*)d_in[1];
    const float* scales = (const float*)d_in[2];
    const float* zeros  = (const float*)d_in[3];
    const float* bias   = (const float*)d_in[4];
    float* out = (float*)d_out;

    qmv_kernel<<<OUT / OPB, TPB>>>(x, qw, scales, zeros, bias, out);
}